// round 14
// baseline (speedup 1.0000x reference)
#include <cuda_runtime.h>
#include <cstddef>

// ---------------------------------------------------------------------------
// HyperNet fused pipeline (R6).
//   K0: fold weights -> g_Wcat[97][1024]   (row 96 = fused bias)
//   K1: Acat = [relu(enc@W1) | pol-MLP(mean)]  -> g_Acat[96][NC] (transposed)
//   K2: z = Acat @ Wcat + bias, sigmoid/sample/clip/logprob/entropy epilogue
// ---------------------------------------------------------------------------

#define NC     16384
#define IN_DIM 512
#define P_DIM  1024
#define H_ENC  64
#define H_POL  32
#define F_DIM  96

__device__ float g_Wcat[(F_DIM + 1) * P_DIM];
__device__ float g_Acat[F_DIM * NC];

#define SQRT_VAR      0.22360679774997896f
#define LOGPROB_CONST 592.8218660580586f
#define ENTROPY_CONST -80.82186605805859f

// ---- f32x2 helpers --------------------------------------------------------
__device__ __forceinline__ unsigned long long pack2(float lo, float hi) {
    unsigned long long r;
    asm("mov.b64 %0, {%1, %2};" : "=l"(r) : "f"(lo), "f"(hi));
    return r;
}
__device__ __forceinline__ float2 unpack2(unsigned long long v) {
    float2 r;
    asm("mov.b64 {%0, %1}, %2;" : "=f"(r.x), "=f"(r.y) : "l"(v));
    return r;
}
__device__ __forceinline__ void fma2(unsigned long long& d,
                                     unsigned long long a,
                                     unsigned long long b) {
    asm("fma.rn.f32x2 %0, %1, %2, %0;" : "+l"(d) : "l"(a), "l"(b));
}

// ---- cp.async helpers -----------------------------------------------------
__device__ __forceinline__ void cp16(void* s, const void* g) {
    unsigned sa = (unsigned)__cvta_generic_to_shared(s);
    asm volatile("cp.async.cg.shared.global [%0], [%1], 16;" :: "r"(sa), "l"(g));
}
#define CP_COMMIT() asm volatile("cp.async.commit_group;")
#define CP_WAIT1()  asm volatile("cp.async.wait_group 1;")
#define CP_WAIT0()  asm volatile("cp.async.wait_group 0;")

// ---------------------------------------------------------------------------
// K0 v2: latency-tolerant weight fold. grid (8, 13), block 128.
// Each CTA: 8 rows x 128 cols, K=1024. v rows staged in smem; comb_w column
// values streamed 16-deep (MLP 16) so the ~260cyc L2 latency is overlapped
// by the 8-row FMA + LDS work of each batch.
// ---------------------------------------------------------------------------
__global__ void __launch_bounds__(128) k0_fold(
    const float* __restrict__ enc_w2, const float* __restrict__ pol_w3,
    const float* __restrict__ pol_b3, const float* __restrict__ comb_w,
    const float* __restrict__ comb_b)
{
    __shared__ float vs[8 * P_DIM];          // 32 KB
    const int tid = threadIdx.x;
    const int r0  = blockIdx.y * 8;
    const int j   = blockIdx.x * 128 + tid;

    // stage 8 source rows (float4, coalesced)
#pragma unroll
    for (int t = 0; t < 16; t++) {
        const int i = tid + t * 128;         // float4 index 0..2047
        const int r = i >> 8, q = i & 255;
        int rr = r0 + r; if (rr > F_DIM) rr = F_DIM;
        const float* src = (rr < 64) ? (enc_w2 + (size_t)rr * P_DIM)
                         : (rr < 96) ? (pol_w3 + (size_t)(rr - 64) * P_DIM)
                                     : pol_b3;
        ((float4*)vs)[i] = ((const float4*)src)[q];
    }
    __syncthreads();

    const float* cw = comb_w + ((r0 >= 64) ? (size_t)P_DIM * P_DIM : 0) + j;

    float acc[8] = {0.f, 0.f, 0.f, 0.f, 0.f, 0.f, 0.f, 0.f};
#pragma unroll 1
    for (int p0 = 0; p0 < P_DIM; p0 += 16) {
        float c[16];
#pragma unroll
        for (int t = 0; t < 16; t++) c[t] = cw[(size_t)(p0 + t) * P_DIM];
#pragma unroll
        for (int t = 0; t < 16; t++) {
#pragma unroll
            for (int r = 0; r < 8; r++)
                acc[r] += vs[r * P_DIM + p0 + t] * c[t];
        }
    }

#pragma unroll
    for (int r = 0; r < 8; r++) {
        const int rr = r0 + r;
        if (rr < F_DIM)        g_Wcat[rr * P_DIM + j] = acc[r];
        else if (rr == F_DIM)  g_Wcat[F_DIM * P_DIM + j] = acc[r] + comb_b[j];
    }
}

// ---------------------------------------------------------------------------
// K1 v2: 32 clients/CTA, 256 threads, grid 512.
// Chunked (128-k) double-buffered cp.async staging of BOTH activations and
// weights; all inner loads are LDS (weights conflict-free, data broadcast,
// float4 over k). smem = 112.4 KB -> 2 CTAs/SM (16 warps).
// ---------------------------------------------------------------------------
#define K1_SW_OFF  8192                       // sD: [2][32*128]
#define K1_SH1_OFF (K1_SW_OFF + 16384)        // sW: [2][8192]
#define K1_SAC_OFF (K1_SH1_OFF + 1024)        // sH1: 32*32
#define K1_FLOATS  (K1_SAC_OFF + F_DIM * 33)  // sAc: 96*33
#define K1_BYTES   (K1_FLOATS * 4)

__global__ void __launch_bounds__(256) k1_acat(
    const float* __restrict__ enc, const float* __restrict__ mean,
    const float* __restrict__ w1,  const float* __restrict__ pw1,
    const float* __restrict__ pb1, const float* __restrict__ pw2,
    const float* __restrict__ pb2)
{
    extern __shared__ float sm[];
    float* sD  = sm;
    float* sW  = sm + K1_SW_OFF;
    float* sH1 = sm + K1_SH1_OFF;
    float* sAc = sm + K1_SAC_OFF;

    const int tid  = threadIdx.x;
    const int base = blockIdx.x * 32;

    auto stage_enc = [&](int ch, int b) {
        const float* eb = enc + (size_t)base * IN_DIM + ch * 128;
#pragma unroll
        for (int t = 0; t < 4; t++) {
            const int i = tid + t * 256, r = i >> 5, q = i & 31;
            cp16(sD + b * 4096 + r * 128 + q * 4,
                 eb + (size_t)r * IN_DIM + q * 4);
        }
        const float* wb = w1 + (size_t)(ch * 128) * H_ENC;
#pragma unroll
        for (int t = 0; t < 8; t++) {
            const int i = tid + t * 256, kk = i >> 4, q = i & 15;
            cp16(sW + b * 8192 + kk * 64 + q * 4,
                 wb + (size_t)kk * 64 + q * 4);
        }
        CP_COMMIT();
    };
    auto stage_pol = [&](int ch, int b) {
        const float* mb = mean + (size_t)base * P_DIM + ch * 128;
#pragma unroll
        for (int t = 0; t < 4; t++) {
            const int i = tid + t * 256, r = i >> 5, q = i & 31;
            cp16(sD + b * 4096 + r * 128 + q * 4,
                 mb + (size_t)r * P_DIM + q * 4);
        }
        const float* wb = pw1 + (size_t)(ch * 128) * H_POL;
#pragma unroll
        for (int t = 0; t < 4; t++) {
            const int i = tid + t * 256, kk = i >> 3, q = i & 7;
            cp16(sW + b * 8192 + kk * 32 + q * 4,
                 wb + (size_t)kk * 32 + q * 4);
        }
        CP_COMMIT();
    };

    // ===== Phase A: enc GEMM, A[32][64] = relu(enc @ w1), K=512 (4 chunks)
    const int h = tid & 63, g = tid >> 6;     // col, 4 row-groups x 8 rows
    float accA[8] = {0.f, 0.f, 0.f, 0.f, 0.f, 0.f, 0.f, 0.f};

    stage_enc(0, 0);
    for (int ch = 0; ch < 4; ch++) {
        const int b = ch & 1;
        if (ch + 1 < 4) { stage_enc(ch + 1, b ^ 1); CP_WAIT1(); }
        else            { CP_WAIT0(); }
        __syncthreads();

        const float* es = sD + b * 4096 + (g * 8) * 128;
        const float* ws = sW + b * 8192 + h;
#pragma unroll 2
        for (int kb = 0; kb < 128; kb += 4) {
            const float w0 = ws[(kb + 0) * 64], wv1 = ws[(kb + 1) * 64];
            const float w2 = ws[(kb + 2) * 64], w3  = ws[(kb + 3) * 64];
#pragma unroll
            for (int r = 0; r < 8; r++) {
                const float4 e = *(const float4*)(es + r * 128 + kb);
                accA[r] += e.x * w0;
                accA[r] += e.y * wv1;
                accA[r] += e.z * w2;
                accA[r] += e.w * w3;
            }
        }
        __syncthreads();
    }
#pragma unroll
    for (int r = 0; r < 8; r++)
        sAc[h * 33 + g * 8 + r] = fmaxf(accA[r], 0.f);

    // ===== Phase B: pol1, h1[32][32] = relu(mean @ pw1 + b1), K=1024 (8 ch)
    const int hc = tid & 31, g2 = tid >> 5;   // col, 8 row-groups x 4 rows
    float accB[4] = {0.f, 0.f, 0.f, 0.f};

    stage_pol(0, 0);
    for (int ch = 0; ch < 8; ch++) {
        const int b = ch & 1;
        if (ch + 1 < 8) { stage_pol(ch + 1, b ^ 1); CP_WAIT1(); }
        else            { CP_WAIT0(); }
        __syncthreads();

        const float* ms = sD + b * 4096 + (g2 * 4) * 128;
        const float* ws = sW + b * 8192 + hc;
#pragma unroll 2
        for (int kb = 0; kb < 128; kb += 4) {
            const float w0 = ws[(kb + 0) * 32], wv1 = ws[(kb + 1) * 32];
            const float w2 = ws[(kb + 2) * 32], w3  = ws[(kb + 3) * 32];
#pragma unroll
            for (int r = 0; r < 4; r++) {
                const float4 m4 = *(const float4*)(ms + r * 128 + kb);
                accB[r] += m4.x * w0;
                accB[r] += m4.y * wv1;
                accB[r] += m4.z * w2;
                accB[r] += m4.w * w3;
            }
        }
        __syncthreads();
    }
    {
        const float bb = pb1[hc];
#pragma unroll
        for (int r = 0; r < 4; r++)
            sH1[(g2 * 4 + r) * H_POL + hc] = fmaxf(accB[r] + bb, 0.f);
    }
    __syncthreads();

    // ===== pol2: h2 = relu(h1 @ pw2 + b2), K=32 (pw2 = 4KB, unrolled LDG)
    {
        float acc[4] = {0.f, 0.f, 0.f, 0.f};
#pragma unroll
        for (int k = 0; k < H_POL; k++) {
            const float w = pw2[k * H_POL + hc];
#pragma unroll
            for (int r = 0; r < 4; r++)
                acc[r] += sH1[(g2 * 4 + r) * H_POL + k] * w;
        }
        const float bb = pb2[hc];
#pragma unroll
        for (int r = 0; r < 4; r++)
            sAc[(64 + hc) * 33 + g2 * 4 + r] = fmaxf(acc[r] + bb, 0.f);
    }
    __syncthreads();

    // ===== write Acat transposed: g_Acat[feature][client] (coalesced)
    for (int i = tid; i < F_DIM * 32; i += 256) {
        const int r = i >> 5, m = i & 31;
        g_Acat[(size_t)r * NC + base + m] = sAc[r * 33 + m];
    }
}

// ---------------------------------------------------------------------------
// K2 v2: 32 clients/CTA, 512 threads (2 cols each), grid 512.
// f32x2 packed FMAs over client row-pairs; Wcat streamed once per CTA
// (halved L2 traffic vs 16-client tiles). FFMA2-pipe bound.
// ---------------------------------------------------------------------------
__global__ void __launch_bounds__(512, 1) k2_final(
    const float* __restrict__ eps,
    float* __restrict__ out_sample,
    float* __restrict__ out_logprob,
    float* __restrict__ out_entropy)
{
    __shared__ float aT[F_DIM * 32];          // 12 KB; reused as reduce buffer

    const int tid = threadIdx.x;
    const int m0  = blockIdx.x * 32;

#pragma unroll
    for (int t = 0; t < 6; t++) {
        const int i = tid + t * 512;
        const int r = i >> 5, m = i & 31;
        aT[i] = g_Acat[(size_t)r * NC + m0 + m];
    }
    __syncthreads();

    const int j0 = tid * 2;

    unsigned long long acc[16][2];
#pragma unroll
    for (int rp = 0; rp < 16; rp++) { acc[rp][0] = 0ull; acc[rp][1] = 0ull; }

#pragma unroll 4
    for (int r = 0; r < F_DIM; r++) {
        const float2 w = *(const float2*)(g_Wcat + r * P_DIM + j0);
        const unsigned long long wx = pack2(w.x, w.x);
        const unsigned long long wy = pack2(w.y, w.y);
#pragma unroll
        for (int rp = 0; rp < 16; rp++) {
            const unsigned long long a2 =
                *(const unsigned long long*)(aT + r * 32 + 2 * rp);
            fma2(acc[rp][0], a2, wx);
            fma2(acc[rp][1], a2, wy);
        }
    }
    __syncthreads();   // before reusing aT as reduction scratch

    const float2 b2  = *(const float2*)(g_Wcat + F_DIM * P_DIM + j0);
    const int wid  = tid >> 5;
    const int lane = tid & 31;

#pragma unroll
    for (int rp = 0; rp < 16; rp++) {
        const float2 zx = unpack2(acc[rp][0]);   // rows (2rp, 2rp+1), col j0
        const float2 zy = unpack2(acc[rp][1]);   // rows (2rp, 2rp+1), col j0+1
#pragma unroll
        for (int hh = 0; hh < 2; hh++) {
            const int row = 2 * rp + hh;
            const float z0 = (hh ? zx.y : zx.x) + b2.x;
            const float z1 = (hh ? zy.y : zy.x) + b2.y;

            const float2 e2 =
                *(const float2*)(eps + (size_t)(m0 + row) * P_DIM + j0);

            const float mv0 = __fdividef(1.f, 1.f + __expf(-z0));
            const float mv1 = __fdividef(1.f, 1.f + __expf(-z1));
            const float s0 = fminf(fmaxf(mv0 + SQRT_VAR * e2.x, 0.f), 1.f);
            const float s1 = fminf(fmaxf(mv1 + SQRT_VAR * e2.y, 0.f), 1.f);

            float2 o; o.x = s0; o.y = s1;
            *(float2*)(out_sample + (size_t)(m0 + row) * P_DIM + j0) = o;

            const float d0 = s0 - mv0, d1 = s1 - mv1;
            float ss = d0 * d0 + d1 * d1;
#pragma unroll
            for (int off = 16; off; off >>= 1)
                ss += __shfl_xor_sync(0xffffffffu, ss, off);
            if (lane == 0) aT[row * 16 + wid] = ss;
        }
    }
    __syncthreads();

    if (tid < 32) {
        float s = 0.f;
#pragma unroll
        for (int w = 0; w < 16; w++) s += aT[tid * 16 + w];
        out_logprob[m0 + tid] = -10.0f * s + LOGPROB_CONST;   // -0.5/VAR
        out_entropy[m0 + tid] = ENTROPY_CONST;
    }
}

// ---------------------------------------------------------------------------
extern "C" void kernel_launch(void* const* d_in, const int* in_sizes, int n_in,
                              void* d_out, int out_size) {
    const float* encoding = (const float*)d_in[0];
    const float* mean     = (const float*)d_in[1];
    const float* enc_w1   = (const float*)d_in[2];
    const float* enc_w2   = (const float*)d_in[3];
    const float* pol_w1   = (const float*)d_in[4];
    const float* pol_b1   = (const float*)d_in[5];
    const float* pol_w2   = (const float*)d_in[6];
    const float* pol_b2   = (const float*)d_in[7];
    const float* pol_w3   = (const float*)d_in[8];
    const float* pol_b3   = (const float*)d_in[9];
    const float* comb_w   = (const float*)d_in[10];
    const float* comb_b   = (const float*)d_in[11];
    const float* eps      = (const float*)d_in[12];

    float* out         = (float*)d_out;
    float* out_sample  = out;                              // [N, 1024]
    float* out_logprob = out + (size_t)NC * P_DIM;         // [N]
    float* out_entropy = out_logprob + NC;                 // [N]

    cudaFuncSetAttribute(k1_acat,
                         cudaFuncAttributeMaxDynamicSharedMemorySize,
                         K1_BYTES);

    k0_fold<<<dim3(8, 13), 128>>>(enc_w2, pol_w3, pol_b3, comb_w, comb_b);
    k1_acat<<<NC / 32, 256, K1_BYTES>>>(encoding, mean, enc_w1,
                                        pol_w1, pol_b1, pol_w2, pol_b2);
    k2_final<<<NC / 32, 512>>>(eps, out_sample, out_logprob, out_entropy);
}

// round 15
// speedup vs baseline: 1.0014x; 1.0014x over previous
#include <cuda_runtime.h>
#include <cstddef>

// ---------------------------------------------------------------------------
// HyperNet fused pipeline (R6).
//   K0: fold weights -> g_Wcat[97][1024]   (row 96 = fused bias)
//   K1: Acat = [relu(enc@W1) | pol-MLP(mean)]  -> g_Acat[96][NC] (transposed)
//   K2: z = Acat @ Wcat + bias, sigmoid/sample/clip/logprob/entropy epilogue
// ---------------------------------------------------------------------------

#define NC     16384
#define IN_DIM 512
#define P_DIM  1024
#define H_ENC  64
#define H_POL  32
#define F_DIM  96

__device__ float g_Wcat[(F_DIM + 1) * P_DIM];
__device__ float g_Acat[F_DIM * NC];

#define SQRT_VAR      0.22360679774997896f
#define LOGPROB_CONST 592.8218660580586f
#define ENTROPY_CONST -80.82186605805859f

// ---- f32x2 helpers --------------------------------------------------------
__device__ __forceinline__ unsigned long long pack2(float lo, float hi) {
    unsigned long long r;
    asm("mov.b64 %0, {%1, %2};" : "=l"(r) : "f"(lo), "f"(hi));
    return r;
}
__device__ __forceinline__ float2 unpack2(unsigned long long v) {
    float2 r;
    asm("mov.b64 {%0, %1}, %2;" : "=f"(r.x), "=f"(r.y) : "l"(v));
    return r;
}
__device__ __forceinline__ void fma2(unsigned long long& d,
                                     unsigned long long a,
                                     unsigned long long b) {
    asm("fma.rn.f32x2 %0, %1, %2, %0;" : "+l"(d) : "l"(a), "l"(b));
}

// ---- cp.async helpers -----------------------------------------------------
__device__ __forceinline__ void cp16(void* s, const void* g) {
    unsigned sa = (unsigned)__cvta_generic_to_shared(s);
    asm volatile("cp.async.cg.shared.global [%0], [%1], 16;" :: "r"(sa), "l"(g));
}
#define CP_COMMIT() asm volatile("cp.async.commit_group;")
#define CP_WAIT1()  asm volatile("cp.async.wait_group 1;")
#define CP_WAIT0()  asm volatile("cp.async.wait_group 0;")

// ---------------------------------------------------------------------------
// K0 v2: latency-tolerant weight fold. grid (8, 13), block 128.
// Each CTA: 8 rows x 128 cols, K=1024. v rows staged in smem; comb_w column
// values streamed 16-deep (MLP 16) so the ~260cyc L2 latency is overlapped
// by the 8-row FMA + LDS work of each batch.
// ---------------------------------------------------------------------------
__global__ void __launch_bounds__(128) k0_fold(
    const float* __restrict__ enc_w2, const float* __restrict__ pol_w3,
    const float* __restrict__ pol_b3, const float* __restrict__ comb_w,
    const float* __restrict__ comb_b)
{
    __shared__ float vs[8 * P_DIM];          // 32 KB
    const int tid = threadIdx.x;
    const int r0  = blockIdx.y * 8;
    const int j   = blockIdx.x * 128 + tid;

    // stage 8 source rows (float4, coalesced)
#pragma unroll
    for (int t = 0; t < 16; t++) {
        const int i = tid + t * 128;         // float4 index 0..2047
        const int r = i >> 8, q = i & 255;
        int rr = r0 + r; if (rr > F_DIM) rr = F_DIM;
        const float* src = (rr < 64) ? (enc_w2 + (size_t)rr * P_DIM)
                         : (rr < 96) ? (pol_w3 + (size_t)(rr - 64) * P_DIM)
                                     : pol_b3;
        ((float4*)vs)[i] = ((const float4*)src)[q];
    }
    __syncthreads();

    const float* cw = comb_w + ((r0 >= 64) ? (size_t)P_DIM * P_DIM : 0) + j;

    float acc[8] = {0.f, 0.f, 0.f, 0.f, 0.f, 0.f, 0.f, 0.f};
#pragma unroll 1
    for (int p0 = 0; p0 < P_DIM; p0 += 16) {
        float c[16];
#pragma unroll
        for (int t = 0; t < 16; t++) c[t] = cw[(size_t)(p0 + t) * P_DIM];
#pragma unroll
        for (int t = 0; t < 16; t++) {
#pragma unroll
            for (int r = 0; r < 8; r++)
                acc[r] += vs[r * P_DIM + p0 + t] * c[t];
        }
    }

#pragma unroll
    for (int r = 0; r < 8; r++) {
        const int rr = r0 + r;
        if (rr < F_DIM)        g_Wcat[rr * P_DIM + j] = acc[r];
        else if (rr == F_DIM)  g_Wcat[F_DIM * P_DIM + j] = acc[r] + comb_b[j];
    }
}

// ---------------------------------------------------------------------------
// K1 v2: 32 clients/CTA, 256 threads, grid 512.
// Chunked (128-k) double-buffered cp.async staging of BOTH activations and
// weights; all inner loads are LDS (weights conflict-free, data broadcast,
// float4 over k). smem = 112.4 KB -> 2 CTAs/SM (16 warps).
// ---------------------------------------------------------------------------
#define K1_SW_OFF  8192                       // sD: [2][32*128]
#define K1_SH1_OFF (K1_SW_OFF + 16384)        // sW: [2][8192]
#define K1_SAC_OFF (K1_SH1_OFF + 1024)        // sH1: 32*32
#define K1_FLOATS  (K1_SAC_OFF + F_DIM * 33)  // sAc: 96*33
#define K1_BYTES   (K1_FLOATS * 4)

__global__ void __launch_bounds__(256) k1_acat(
    const float* __restrict__ enc, const float* __restrict__ mean,
    const float* __restrict__ w1,  const float* __restrict__ pw1,
    const float* __restrict__ pb1, const float* __restrict__ pw2,
    const float* __restrict__ pb2)
{
    extern __shared__ float sm[];
    float* sD  = sm;
    float* sW  = sm + K1_SW_OFF;
    float* sH1 = sm + K1_SH1_OFF;
    float* sAc = sm + K1_SAC_OFF;

    const int tid  = threadIdx.x;
    const int base = blockIdx.x * 32;

    auto stage_enc = [&](int ch, int b) {
        const float* eb = enc + (size_t)base * IN_DIM + ch * 128;
#pragma unroll
        for (int t = 0; t < 4; t++) {
            const int i = tid + t * 256, r = i >> 5, q = i & 31;
            cp16(sD + b * 4096 + r * 128 + q * 4,
                 eb + (size_t)r * IN_DIM + q * 4);
        }
        const float* wb = w1 + (size_t)(ch * 128) * H_ENC;
#pragma unroll
        for (int t = 0; t < 8; t++) {
            const int i = tid + t * 256, kk = i >> 4, q = i & 15;
            cp16(sW + b * 8192 + kk * 64 + q * 4,
                 wb + (size_t)kk * 64 + q * 4);
        }
        CP_COMMIT();
    };
    auto stage_pol = [&](int ch, int b) {
        const float* mb = mean + (size_t)base * P_DIM + ch * 128;
#pragma unroll
        for (int t = 0; t < 4; t++) {
            const int i = tid + t * 256, r = i >> 5, q = i & 31;
            cp16(sD + b * 4096 + r * 128 + q * 4,
                 mb + (size_t)r * P_DIM + q * 4);
        }
        const float* wb = pw1 + (size_t)(ch * 128) * H_POL;
#pragma unroll
        for (int t = 0; t < 4; t++) {
            const int i = tid + t * 256, kk = i >> 3, q = i & 7;
            cp16(sW + b * 8192 + kk * 32 + q * 4,
                 wb + (size_t)kk * 32 + q * 4);
        }
        CP_COMMIT();
    };

    // ===== Phase A: enc GEMM, A[32][64] = relu(enc @ w1), K=512 (4 chunks)
    const int h = tid & 63, g = tid >> 6;     // col, 4 row-groups x 8 rows
    float accA[8] = {0.f, 0.f, 0.f, 0.f, 0.f, 0.f, 0.f, 0.f};

    stage_enc(0, 0);
    for (int ch = 0; ch < 4; ch++) {
        const int b = ch & 1;
        if (ch + 1 < 4) { stage_enc(ch + 1, b ^ 1); CP_WAIT1(); }
        else            { CP_WAIT0(); }
        __syncthreads();

        const float* es = sD + b * 4096 + (g * 8) * 128;
        const float* ws = sW + b * 8192 + h;
#pragma unroll 2
        for (int kb = 0; kb < 128; kb += 4) {
            const float w0 = ws[(kb + 0) * 64], wv1 = ws[(kb + 1) * 64];
            const float w2 = ws[(kb + 2) * 64], w3  = ws[(kb + 3) * 64];
#pragma unroll
            for (int r = 0; r < 8; r++) {
                const float4 e = *(const float4*)(es + r * 128 + kb);
                accA[r] += e.x * w0;
                accA[r] += e.y * wv1;
                accA[r] += e.z * w2;
                accA[r] += e.w * w3;
            }
        }
        __syncthreads();
    }
#pragma unroll
    for (int r = 0; r < 8; r++)
        sAc[h * 33 + g * 8 + r] = fmaxf(accA[r], 0.f);

    // ===== Phase B: pol1, h1[32][32] = relu(mean @ pw1 + b1), K=1024 (8 ch)
    const int hc = tid & 31, g2 = tid >> 5;   // col, 8 row-groups x 4 rows
    float accB[4] = {0.f, 0.f, 0.f, 0.f};

    stage_pol(0, 0);
    for (int ch = 0; ch < 8; ch++) {
        const int b = ch & 1;
        if (ch + 1 < 8) { stage_pol(ch + 1, b ^ 1); CP_WAIT1(); }
        else            { CP_WAIT0(); }
        __syncthreads();

        const float* ms = sD + b * 4096 + (g2 * 4) * 128;
        const float* ws = sW + b * 8192 + hc;
#pragma unroll 2
        for (int kb = 0; kb < 128; kb += 4) {
            const float w0 = ws[(kb + 0) * 32], wv1 = ws[(kb + 1) * 32];
            const float w2 = ws[(kb + 2) * 32], w3  = ws[(kb + 3) * 32];
#pragma unroll
            for (int r = 0; r < 4; r++) {
                const float4 m4 = *(const float4*)(ms + r * 128 + kb);
                accB[r] += m4.x * w0;
                accB[r] += m4.y * wv1;
                accB[r] += m4.z * w2;
                accB[r] += m4.w * w3;
            }
        }
        __syncthreads();
    }
    {
        const float bb = pb1[hc];
#pragma unroll
        for (int r = 0; r < 4; r++)
            sH1[(g2 * 4 + r) * H_POL + hc] = fmaxf(accB[r] + bb, 0.f);
    }
    __syncthreads();

    // ===== pol2: h2 = relu(h1 @ pw2 + b2), K=32 (pw2 = 4KB, unrolled LDG)
    {
        float acc[4] = {0.f, 0.f, 0.f, 0.f};
#pragma unroll
        for (int k = 0; k < H_POL; k++) {
            const float w = pw2[k * H_POL + hc];
#pragma unroll
            for (int r = 0; r < 4; r++)
                acc[r] += sH1[(g2 * 4 + r) * H_POL + k] * w;
        }
        const float bb = pb2[hc];
#pragma unroll
        for (int r = 0; r < 4; r++)
            sAc[(64 + hc) * 33 + g2 * 4 + r] = fmaxf(acc[r] + bb, 0.f);
    }
    __syncthreads();

    // ===== write Acat transposed: g_Acat[feature][client] (coalesced)
    for (int i = tid; i < F_DIM * 32; i += 256) {
        const int r = i >> 5, m = i & 31;
        g_Acat[(size_t)r * NC + base + m] = sAc[r * 33 + m];
    }
}

// ---------------------------------------------------------------------------
// K2 v2: 32 clients/CTA, 512 threads (2 cols each), grid 512.
// f32x2 packed FMAs over client row-pairs; Wcat streamed once per CTA
// (halved L2 traffic vs 16-client tiles). FFMA2-pipe bound.
// ---------------------------------------------------------------------------
__global__ void __launch_bounds__(512, 1) k2_final(
    const float* __restrict__ eps,
    float* __restrict__ out_sample,
    float* __restrict__ out_logprob,
    float* __restrict__ out_entropy)
{
    __shared__ float aT[F_DIM * 32];          // 12 KB; reused as reduce buffer

    const int tid = threadIdx.x;
    const int m0  = blockIdx.x * 32;

#pragma unroll
    for (int t = 0; t < 6; t++) {
        const int i = tid + t * 512;
        const int r = i >> 5, m = i & 31;
        aT[i] = g_Acat[(size_t)r * NC + m0 + m];
    }
    __syncthreads();

    const int j0 = tid * 2;

    unsigned long long acc[16][2];
#pragma unroll
    for (int rp = 0; rp < 16; rp++) { acc[rp][0] = 0ull; acc[rp][1] = 0ull; }

#pragma unroll 4
    for (int r = 0; r < F_DIM; r++) {
        const float2 w = *(const float2*)(g_Wcat + r * P_DIM + j0);
        const unsigned long long wx = pack2(w.x, w.x);
        const unsigned long long wy = pack2(w.y, w.y);
#pragma unroll
        for (int rp = 0; rp < 16; rp++) {
            const unsigned long long a2 =
                *(const unsigned long long*)(aT + r * 32 + 2 * rp);
            fma2(acc[rp][0], a2, wx);
            fma2(acc[rp][1], a2, wy);
        }
    }
    __syncthreads();   // before reusing aT as reduction scratch

    const float2 b2  = *(const float2*)(g_Wcat + F_DIM * P_DIM + j0);
    const int wid  = tid >> 5;
    const int lane = tid & 31;

#pragma unroll
    for (int rp = 0; rp < 16; rp++) {
        const float2 zx = unpack2(acc[rp][0]);   // rows (2rp, 2rp+1), col j0
        const float2 zy = unpack2(acc[rp][1]);   // rows (2rp, 2rp+1), col j0+1
#pragma unroll
        for (int hh = 0; hh < 2; hh++) {
            const int row = 2 * rp + hh;
            const float z0 = (hh ? zx.y : zx.x) + b2.x;
            const float z1 = (hh ? zy.y : zy.x) + b2.y;

            const float2 e2 =
                *(const float2*)(eps + (size_t)(m0 + row) * P_DIM + j0);

            const float mv0 = __fdividef(1.f, 1.f + __expf(-z0));
            const float mv1 = __fdividef(1.f, 1.f + __expf(-z1));
            const float s0 = fminf(fmaxf(mv0 + SQRT_VAR * e2.x, 0.f), 1.f);
            const float s1 = fminf(fmaxf(mv1 + SQRT_VAR * e2.y, 0.f), 1.f);

            float2 o; o.x = s0; o.y = s1;
            *(float2*)(out_sample + (size_t)(m0 + row) * P_DIM + j0) = o;

            const float d0 = s0 - mv0, d1 = s1 - mv1;
            float ss = d0 * d0 + d1 * d1;
#pragma unroll
            for (int off = 16; off; off >>= 1)
                ss += __shfl_xor_sync(0xffffffffu, ss, off);
            if (lane == 0) aT[row * 16 + wid] = ss;
        }
    }
    __syncthreads();

    if (tid < 32) {
        float s = 0.f;
#pragma unroll
        for (int w = 0; w < 16; w++) s += aT[tid * 16 + w];
        out_logprob[m0 + tid] = -10.0f * s + LOGPROB_CONST;   // -0.5/VAR
        out_entropy[m0 + tid] = ENTROPY_CONST;
    }
}

// ---------------------------------------------------------------------------
extern "C" void kernel_launch(void* const* d_in, const int* in_sizes, int n_in,
                              void* d_out, int out_size) {
    const float* encoding = (const float*)d_in[0];
    const float* mean     = (const float*)d_in[1];
    const float* enc_w1   = (const float*)d_in[2];
    const float* enc_w2   = (const float*)d_in[3];
    const float* pol_w1   = (const float*)d_in[4];
    const float* pol_b1   = (const float*)d_in[5];
    const float* pol_w2   = (const float*)d_in[6];
    const float* pol_b2   = (const float*)d_in[7];
    const float* pol_w3   = (const float*)d_in[8];
    const float* pol_b3   = (const float*)d_in[9];
    const float* comb_w   = (const float*)d_in[10];
    const float* comb_b   = (const float*)d_in[11];
    const float* eps      = (const float*)d_in[12];

    float* out         = (float*)d_out;
    float* out_sample  = out;                              // [N, 1024]
    float* out_logprob = out + (size_t)NC * P_DIM;         // [N]
    float* out_entropy = out_logprob + NC;                 // [N]

    cudaFuncSetAttribute(k1_acat,
                         cudaFuncAttributeMaxDynamicSharedMemorySize,
                         K1_BYTES);

    k0_fold<<<dim3(8, 13), 128>>>(enc_w2, pol_w3, pol_b3, comb_w, comb_b);
    k1_acat<<<NC / 32, 256, K1_BYTES>>>(encoding, mean, enc_w1,
                                        pol_w1, pol_b1, pol_w2, pol_b2);
    k2_final<<<NC / 32, 512>>>(eps, out_sample, out_logprob, out_entropy);
}